// round 1
// baseline (speedup 1.0000x reference)
#include <cuda_runtime.h>
#include <math.h>

// Problem constants
#define BB 64
#define TT 512
#define II 128
#define HH 512
#define OO 64
#define ALPHA 0.1f

// Recurrent kernel config
#define GRID_R 128   // blocks; each owns JT=4 hidden columns
#define JT 4
#define NTH_R 512    // 16 warps; warp w owns batches 4w..4w+3

// Scratch: full hidden history [T][B][H] (64 MB) — static device array (allowed)
__device__ float g_hist[(size_t)TT * BB * HH];
__device__ unsigned g_cnt;

__global__ void reset_kernel() { g_cnt = 0u; }

__device__ __forceinline__ float4 ldcg4(const float* p) {
    return __ldcg(reinterpret_cast<const float4*>(p));
}

__global__ void __launch_bounds__(NTH_R, 1) rnn_recurrent(
    const float* __restrict__ x,     // [B][T][I]
    const float* __restrict__ h0,    // [B][H]
    const float* __restrict__ Win,   // [H][I]
    const float* __restrict__ Wrec,  // [H][H]
    const float* __restrict__ bias)  // [H]
{
    const int tid  = threadIdx.x;
    const int warp = tid >> 5;
    const int lane = tid & 31;
    const int j0    = blockIdx.x * JT;  // this block's hidden columns
    const int bbase = warp * 4;         // this warp's batches
    const int k0 = lane * 16;           // this lane's W_rec K-chunk
    const int i0 = lane * 4;            // this lane's W_in I-chunk

    // ---- Preload weights into registers ONCE (reused for all 512 steps) ----
    float4 wr[JT][4];  // W_rec[j0+jj][k0 .. k0+15]
    float4 wi[JT];     // W_in [j0+jj][i0 .. i0+3]
#pragma unroll
    for (int jj = 0; jj < JT; jj++) {
#pragma unroll
        for (int c = 0; c < 4; c++)
            wr[jj][c] = *reinterpret_cast<const float4*>(Wrec + (size_t)(j0 + jj) * HH + k0 + c * 4);
        wi[jj] = *reinterpret_cast<const float4*>(Win + (size_t)(j0 + jj) * II + i0);
    }
    float bj = 0.0f;
    if (lane < 16) bj = bias[j0 + (lane & 3)];

    for (int t = 0; t < TT; ++t) {
        const float* hprev = (t == 0) ? h0 : (g_hist + (size_t)(t - 1) * BB * HH);

        float acc[4][JT];
#pragma unroll
        for (int bb = 0; bb < 4; bb++)
#pragma unroll
            for (int jj = 0; jj < JT; jj++) acc[bb][jj] = 0.0f;

#pragma unroll
        for (int bb = 0; bb < 4; bb++) {
            const int bg = bbase + bb;
            const float* hp = hprev + (size_t)bg * HH + k0;
            // recurrent part: h · W_rec^T over this lane's k-chunk
#pragma unroll
            for (int c = 0; c < 4; c++) {
                float4 hv = ldcg4(hp + c * 4);
#pragma unroll
                for (int jj = 0; jj < JT; jj++) {
                    acc[bb][jj] = fmaf(hv.x, wr[jj][c].x, acc[bb][jj]);
                    acc[bb][jj] = fmaf(hv.y, wr[jj][c].y, acc[bb][jj]);
                    acc[bb][jj] = fmaf(hv.z, wr[jj][c].z, acc[bb][jj]);
                    acc[bb][jj] = fmaf(hv.w, wr[jj][c].w, acc[bb][jj]);
                }
            }
            // fused input projection: x_t · W_in^T over this lane's i-chunk
            float4 xv = __ldg(reinterpret_cast<const float4*>(
                x + ((size_t)bg * TT + t) * II + i0));
#pragma unroll
            for (int jj = 0; jj < JT; jj++) {
                acc[bb][jj] = fmaf(xv.x, wi[jj].x, acc[bb][jj]);
                acc[bb][jj] = fmaf(xv.y, wi[jj].y, acc[bb][jj]);
                acc[bb][jj] = fmaf(xv.z, wi[jj].z, acc[bb][jj]);
                acc[bb][jj] = fmaf(xv.w, wi[jj].w, acc[bb][jj]);
            }
        }

        // Butterfly reduce across the 32 lanes (lanes partition K and I)
#pragma unroll
        for (int off = 16; off >= 1; off >>= 1) {
#pragma unroll
            for (int bb = 0; bb < 4; bb++)
#pragma unroll
                for (int jj = 0; jj < JT; jj++)
                    acc[bb][jj] += __shfl_xor_sync(0xffffffffu, acc[bb][jj], off);
        }

        // Epilogue: lanes 0..15 each own one (batch, j) pair
        if (lane < 16) {
            const int bl = lane >> 2, jl = lane & 3;
            const int bg = bbase + bl;
            const int j  = j0 + jl;
            float pre  = acc[bl][jl] + bj;
            float hold = __ldcg(hprev + (size_t)bg * HH + j);
            float hnew = (1.0f - ALPHA) * hold + ALPHA * tanhf(pre);
            __stcg(g_hist + (size_t)t * BB * HH + (size_t)bg * HH + j, hnew);
        }

        // Grid barrier (monotonic ticket counter; all 128 CTAs resident)
        __syncthreads();
        if (t < TT - 1) {
            if (tid == 0) {
                __threadfence();
                atomicAdd(&g_cnt, 1u);
                const unsigned target = (unsigned)(t + 1) * GRID_R;
                while (*((volatile unsigned*)&g_cnt) < target) { }
            }
            __syncthreads();
        }
    }
}

// ---------------- Output projection: out[b][t][o] = hist[t][b] · W_out[o] + b_out[o] ----------------
#define NTH_O 256
#define KC 64  // K chunk staged in shared memory

__global__ void __launch_bounds__(NTH_O) rnn_output(
    const float* __restrict__ Wout,  // [O][H]
    const float* __restrict__ bout,  // [O]
    float* __restrict__ out)         // [B][T][O]
{
    const int t = blockIdx.x;
    __shared__ float sH[BB][KC + 4];  // +4 pad keeps 16B alignment, reduces conflicts
    __shared__ float sW[OO][KC + 4];

    const int tid = threadIdx.x;
    const int og = tid & 15;   // o-group (4 o each)
    const int bg = tid >> 4;   // b-group (4 b each)

    float acc[4][4];
#pragma unroll
    for (int i = 0; i < 4; i++)
#pragma unroll
        for (int j = 0; j < 4; j++) acc[i][j] = 0.0f;

    const float* hrow = g_hist + (size_t)t * BB * HH;

    for (int kc = 0; kc < HH; kc += KC) {
        // Stage hist[t][:, kc:kc+KC] and Wout[:, kc:kc+KC]
        for (int idx = tid; idx < BB * (KC / 4); idx += NTH_O) {
            int row = idx / (KC / 4);
            int c4  = idx % (KC / 4);
            float4 v = *reinterpret_cast<const float4*>(hrow + (size_t)row * HH + kc + c4 * 4);
            sH[row][c4 * 4 + 0] = v.x; sH[row][c4 * 4 + 1] = v.y;
            sH[row][c4 * 4 + 2] = v.z; sH[row][c4 * 4 + 3] = v.w;
        }
        for (int idx = tid; idx < OO * (KC / 4); idx += NTH_O) {
            int row = idx / (KC / 4);
            int c4  = idx % (KC / 4);
            float4 v = *reinterpret_cast<const float4*>(Wout + (size_t)row * HH + kc + c4 * 4);
            sW[row][c4 * 4 + 0] = v.x; sW[row][c4 * 4 + 1] = v.y;
            sW[row][c4 * 4 + 2] = v.z; sW[row][c4 * 4 + 3] = v.w;
        }
        __syncthreads();

#pragma unroll
        for (int k = 0; k < KC; k += 4) {
            float4 hv[4], wv[4];
#pragma unroll
            for (int bb = 0; bb < 4; bb++)
                hv[bb] = *reinterpret_cast<const float4*>(&sH[bg * 4 + bb][k]);
#pragma unroll
            for (int oo = 0; oo < 4; oo++)
                wv[oo] = *reinterpret_cast<const float4*>(&sW[og * 4 + oo][k]);
#pragma unroll
            for (int bb = 0; bb < 4; bb++)
#pragma unroll
                for (int oo = 0; oo < 4; oo++) {
                    acc[bb][oo] = fmaf(hv[bb].x, wv[oo].x, acc[bb][oo]);
                    acc[bb][oo] = fmaf(hv[bb].y, wv[oo].y, acc[bb][oo]);
                    acc[bb][oo] = fmaf(hv[bb].z, wv[oo].z, acc[bb][oo]);
                    acc[bb][oo] = fmaf(hv[bb].w, wv[oo].w, acc[bb][oo]);
                }
        }
        __syncthreads();
    }

#pragma unroll
    for (int oo = 0; oo < 4; oo++) {
        float bo = __ldg(bout + og * 4 + oo);
#pragma unroll
        for (int bb = 0; bb < 4; bb++) {
            int b = bg * 4 + bb;
            int o = og * 4 + oo;
            out[(size_t)b * TT * OO + (size_t)t * OO + o] = acc[bb][oo] + bo;
        }
    }
}

__global__ void copy_hfinal(float* __restrict__ dst) {
    int i = blockIdx.x * blockDim.x + threadIdx.x;
    if (i < BB * HH) dst[i] = g_hist[(size_t)(TT - 1) * BB * HH + i];
}

extern "C" void kernel_launch(void* const* d_in, const int* in_sizes, int n_in,
                              void* d_out, int out_size) {
    const float* x    = (const float*)d_in[0];  // [B][T][I]
    const float* h0   = (const float*)d_in[1];  // [B][H]
    const float* Win  = (const float*)d_in[2];  // [H][I]
    const float* Wrec = (const float*)d_in[3];  // [H][H]
    const float* bias = (const float*)d_in[4];  // [H]
    const float* Wout = (const float*)d_in[5];  // [O][H]
    const float* bout = (const float*)d_in[6];  // [O]
    float* out = (float*)d_out;

    reset_kernel<<<1, 1>>>();
    rnn_recurrent<<<GRID_R, NTH_R>>>(x, h0, Win, Wrec, bias);
    rnn_output<<<TT, NTH_O>>>(Wout, bout, out);
    if (out_size >= BB * TT * OO + BB * HH) {
        copy_hfinal<<<(BB * HH + 255) / 256, 256>>>(out + (size_t)BB * TT * OO);
    }
}